// round 3
// baseline (speedup 1.0000x reference)
#include <cuda_runtime.h>
#include <math.h>
#include <float.h>

#define RES   512
#define HID   128
#define NSEG  (HID + 1)            // 129 outer segments
#define KMAX  (NSEG + HID * NSEG)  // 16641 worst-case final segments
#define KPAD  16642                // even pad so float2 region stays 8B aligned
#define LUTN  8192                 // uniform-grid bins for search acceleration
#define LUTE  (LUTN + 3)           // lut entries j=0..LUTN+2 (1 bin slack each side)

// ---------------- persistent device tables (rebuilt every launch) ----------
__device__ float  g_sorted_t[HID];
__device__ float2 g_ab[NSEG * HID];         // per (outer seg, j): (alpha, beta)
__device__ float  g_kinks[NSEG * HID];      // per outer seg: sorted inner kinks
__device__ int    g_m[NSEG];                // # inner kinks per outer seg
__device__ int    g_off[NSEG];              // flat offsets (exclusive scan)
__device__ int    g_K;                      // final segment count
__device__ float  g_flatT[KMAX];            // sorted global breakpoints
__device__ float2 g_flatAB[KMAX];           // (A, B+b3) per final segment
__device__ unsigned short g_lut[LUTE];      // bin -> segment index lower bound
__device__ float4 g_lutP;                   // (lo, hi, scale, bias)

// ============================================================================
// Setup 1: per outer segment s: sort outer kinks, compute affine coeffs of
// layer-2 preacts, find + sort inner kinks. Branchless & unrolled.
// ============================================================================
__global__ void setup_seg(const float* __restrict__ w1,
                          const float* __restrict__ b1,
                          const float* __restrict__ w2,
                          const float* __restrict__ b2) {
    __shared__ float sw1[HID], sb1[HID], st[HID], ssort[HID], su[HID];
    __shared__ int   sval[HID];
    int j = threadIdx.x;
    int s = blockIdx.x;

    float w = w1[j], b = b1[j];
    sw1[j] = w; sb1[j] = b;
    float t = -b / w;
    st[j] = t;
    __syncthreads();

    int rank = 0;
    #pragma unroll 8
    for (int k = 0; k < HID; k++) {
        float tk = st[k];
        rank += (tk < t) || (tk == t && k < j);
    }
    ssort[rank] = t;
    __syncthreads();
    if (s == 0) g_sorted_t[j] = ssort[j];

    float lo = (s == 0)   ? -FLT_MAX : ssort[s - 1];
    float hi = (s == HID) ?  FLT_MAX : ssort[s];
    float Fm = (s == 0)   ? ssort[0] - 1.0f
             : (s == HID) ? ssort[HID - 1] + 1.0f
                          : 0.5f * (lo + hi);

    float alpha = 0.0f, beta = 0.0f;
    #pragma unroll 16
    for (int i = 0; i < HID; i++) {
        float wi = sw1[i], bi = sb1[i];
        bool act = fmaf(wi, Fm, bi) > 0.0f;
        float w2ij = w2[i * HID + j];
        alpha = fmaf(act ? wi : 0.0f, w2ij, alpha);
        beta  = fmaf(act ? bi : 0.0f, w2ij, beta);
    }
    beta += b2[j];
    g_ab[s * HID + j] = make_float2(alpha, beta);

    float u = -beta / alpha;
    bool valid = (alpha != 0.0f) && (u > lo) && (u < hi);  // NaN -> false
    su[j] = valid ? u : FLT_MAX;
    sval[j] = valid ? 1 : 0;
    __syncthreads();

    int m = 0, r = 0;
    float uj = su[j];
    #pragma unroll 8
    for (int k = 0; k < HID; k++) {
        m += sval[k];
        float uk = su[k];
        r += (uk < uj) || (uk == uj && k < j);
    }
    if (valid) g_kinks[s * HID + r] = u;
    if (j == 0) g_m[s] = m;
}

// ============================================================================
// Setup 2: exclusive scan of per-segment counts -> flat offsets + K.
// ============================================================================
__global__ void setup_scan() {
    __shared__ int sm_m[NSEG];
    int t = threadIdx.x;
    if (t < NSEG) sm_m[t] = g_m[t];
    __syncthreads();
    if (t == 0) {
        int off = 0;
        for (int s = 0; s < NSEG; s++) { g_off[s] = s + off; off += sm_m[s]; }
        g_K = NSEG + off;
    }
}

// ============================================================================
// Setup 3: build flat global table (A,B) per final segment.
// ============================================================================
__global__ void setup_final(const float* __restrict__ w3,
                            const float* __restrict__ b3) {
    int s = blockIdx.x;
    __shared__ int   soff, snsub;
    __shared__ float slo, shi;
    if (threadIdx.x == 0) {
        soff  = g_off[s];
        snsub = g_m[s] + 1;
        slo = (s == 0)   ? -FLT_MAX : g_sorted_t[s - 1];
        shi = (s == HID) ?  FLT_MAX : g_sorted_t[s];
    }
    __syncthreads();
    int   off = soff, nsub = snsub;
    float segLo = slo, segHi = shi;
    float b3v = b3[0];
    int wid = threadIdx.x >> 5, lane = threadIdx.x & 31;

    for (int r = wid; r < nsub; r += 8) {
        float lo_r = (r == 0)        ? segLo : g_kinks[s * HID + r - 1];
        float hi_r = (r == nsub - 1) ? segHi : g_kinks[s * HID + r];
        float Fm;
        if (lo_r == -FLT_MAX)      Fm = hi_r - 1.0f;
        else if (hi_r == FLT_MAX)  Fm = lo_r + 1.0f;
        else                       Fm = 0.5f * (lo_r + hi_r);

        float A = 0.0f, B = 0.0f;
        #pragma unroll
        for (int q = lane; q < HID; q += 32) {
            float2 ab = g_ab[s * HID + q];
            if (fmaf(ab.x, Fm, ab.y) > 0.0f) {
                float w3q = w3[q];
                A = fmaf(w3q, ab.x, A);
                B = fmaf(w3q, ab.y, B);
            }
        }
        #pragma unroll
        for (int d = 16; d; d >>= 1) {
            A += __shfl_xor_sync(0xffffffffu, A, d);
            B += __shfl_xor_sync(0xffffffffu, B, d);
        }
        if (lane == 0) {
            g_flatT[off + r]  = lo_r;
            g_flatAB[off + r] = make_float2(A, B + b3v);
        }
    }
}

// ============================================================================
// Setup 4: uniform-grid LUT over a percentile-trimmed breakpoint range.
// lut[j] = largest s with flatT[s] <= lo + (j-1)*step  (one bin of slack).
// ============================================================================
__global__ void setup_lut() {
    int j = blockIdx.x * blockDim.x + threadIdx.x;
    if (j >= LUTE) return;
    int K = g_K;
    int trim = K >> 6; if (trim < 1) trim = 1;
    float lo = g_flatT[trim];
    float hi = g_flatT[K - 1 - trim];
    if (!(hi > lo)) hi = lo + 1.0f;
    float step = (hi - lo) * (1.0f / (float)LUTN);
    float target = fmaf((float)(j - 1), step, lo);

    int a = 0, b = K - 1;
    while (a < b) {
        int mid = (a + b + 1) >> 1;
        if (g_flatT[mid] <= target) a = mid; else b = mid - 1;
    }
    g_lut[j] = (unsigned short)a;
    if (j == 0) {
        float scale = (float)LUTN / (hi - lo);
        g_lutP = make_float4(lo, hi, scale, -lo * scale);
    }
}

// ============================================================================
// Main kernel
// ============================================================================
__device__ __forceinline__ float interp_fast(const float* __restrict__ pl,
                                             int i1, float h, int i2, float v) {
    const float* p0 = pl + i1 * RES + i2;
    float bl = p0[0];        // [i1  ][i2  ]
    float tl = p0[1];        // [i1  ][i2+1]
    float br = p0[RES];      // [i1+1][i2  ]
    float tr = p0[RES + 1];  // [i1+1][i2+1]
    float bottom = fmaf(br - bl, h, bl);
    float top    = fmaf(tr - tl, h, tl);
    return fmaf(top - bottom, v, bottom);
}

__device__ __forceinline__ float eval_point(
    float px, float py, float pz,
    const float* __restrict__ xy, const float* __restrict__ yz,
    const float* __restrict__ xz,
    const float* sT, const float2* sAB, const unsigned short* sLut,
    float loV, float hiV, float scale, float bias, int Km1) {

    float cx = fmaf(px, 255.5f, 255.5f);   // (p+1)*0.5*511, in [0,511)
    float cy = fmaf(py, 255.5f, 255.5f);
    float cz = fmaf(pz, 255.5f, 255.5f);
    int ix = min((int)cx, RES - 2);        // truncation == floor (cx >= 0)
    int iy = min((int)cy, RES - 2);
    int iz = min((int)cz, RES - 2);
    float hx = cx - (float)ix;
    float hy = cy - (float)iy;
    float hz = cz - (float)iz;

    float F = interp_fast(xy, ix, hx, iy, hy)
            + interp_fast(xz, ix, hx, iz, hz)
            + interp_fast(yz, iy, hy, iz, hz);

    int b = __float2int_rd(fmaf(F, scale, bias));
    b = min(max(b, 0), LUTN - 1);
    int lo = (F <  loV) ? 0   : (int)sLut[b];
    int hi = (F >= hiV) ? Km1 : (int)sLut[b + 2];
    while (lo < hi) {
        int mid = (lo + hi + 1) >> 1;
        bool le = sT[mid] <= F;
        lo = le ? mid : lo;
        hi = le ? hi  : mid - 1;
    }
    float2 ab = sAB[lo];
    float r;
    asm("tanh.approx.f32 %0, %1;" : "=f"(r) : "f"(fmaf(ab.x, F, ab.y)));
    return r;
}

__global__ __launch_bounds__(1024, 1)
void neusdf_main(const float* __restrict__ points,
                 const float* __restrict__ xy,
                 const float* __restrict__ yz,
                 const float* __restrict__ xz,
                 float* __restrict__ out, int N) {
    extern __shared__ float sm[];
    float*          sT   = sm;                                  // [K]
    float2*         sAB  = (float2*)(sm + KPAD);                // [K]
    unsigned short* sLut = (unsigned short*)(sm + KPAD + 2 * KMAX);
    __shared__ int    sK;
    __shared__ float4 sP;
    if (threadIdx.x == 0) { sK = g_K; sP = g_lutP; }
    __syncthreads();
    int K = sK;
    for (int i = threadIdx.x; i < K; i += 1024) {
        sT[i]  = g_flatT[i];
        sAB[i] = g_flatAB[i];
    }
    for (int i = threadIdx.x; i < LUTE; i += 1024) sLut[i] = g_lut[i];
    __syncthreads();

    float loV = sP.x, hiV = sP.y, scale = sP.z, bias = sP.w;
    int Km1 = K - 1;

    const float2* pp = (const float2*)points;
    float2*       op = (float2*)out;
    int G = N >> 1;
    int gstride = gridDim.x * blockDim.x;

    for (int g = blockIdx.x * blockDim.x + threadIdx.x; g < G; g += gstride) {
        float2 u = pp[3 * g + 0];
        float2 v = pp[3 * g + 1];
        float2 w = pp[3 * g + 2];
        float o0 = eval_point(u.x, u.y, v.x, xy, yz, xz, sT, sAB, sLut,
                              loV, hiV, scale, bias, Km1);
        float o1 = eval_point(v.y, w.x, w.y, xy, yz, xz, sT, sAB, sLut,
                              loV, hiV, scale, bias, Km1);
        op[g] = make_float2(o0, o1);
    }
    // odd-N tail (N is even for this problem; kept for generality)
    if ((N & 1) && blockIdx.x == 0 && threadIdx.x == 0) {
        int i = N - 1;
        out[i] = eval_point(points[3*i], points[3*i+1], points[3*i+2],
                            xy, yz, xz, sT, sAB, sLut,
                            loV, hiV, scale, bias, Km1);
    }
}

// ============================================================================
extern "C" void kernel_launch(void* const* d_in, const int* in_sizes, int n_in,
                              void* d_out, int out_size) {
    const float* points = (const float*)d_in[0];
    const float* xy     = (const float*)d_in[1];
    const float* yz     = (const float*)d_in[2];
    const float* xz     = (const float*)d_in[3];
    const float* w1     = (const float*)d_in[4];
    const float* b1     = (const float*)d_in[5];
    const float* w2     = (const float*)d_in[6];
    const float* b2     = (const float*)d_in[7];
    const float* w3     = (const float*)d_in[8];
    const float* b3     = (const float*)d_in[9];
    int N = in_sizes[0] / 3;

    setup_seg <<<NSEG, HID>>>(w1, b1, w2, b2);
    setup_scan<<<1, 256>>>();
    setup_final<<<NSEG, 256>>>(w3, b3);
    setup_lut <<<(LUTE + 255) / 256, 256>>>();

    size_t smem = sizeof(float) * KPAD + sizeof(float2) * KMAX
                + sizeof(unsigned short) * (LUTE + 1);
    cudaFuncSetAttribute(neusdf_main,
                         cudaFuncAttributeMaxDynamicSharedMemorySize,
                         (int)smem);

    int nsm = 148;
    cudaDeviceGetAttribute(&nsm, cudaDevAttrMultiProcessorCount, 0);

    neusdf_main<<<nsm, 1024, smem>>>(points, xy, yz, xz, (float*)d_out, N);
}

// round 4
// speedup vs baseline: 1.9029x; 1.9029x over previous
#include <cuda_runtime.h>
#include <math.h>
#include <float.h>

#define RES   512
#define HID   128
#define NSEG  (HID + 1)            // 129 outer segments
#define KMAX  (NSEG + HID * NSEG)  // 16641 worst-case final segments
#define KPAD  16642
#define LUTBITS 13
#define LUTN  (1 << LUTBITS)       // 8192 bins over ordered-float space
#define LUTE  (LUTN + 1)           // 8193 boundary entries

// ---------------- persistent device tables (rebuilt every launch) ----------
__device__ float  g_sorted_t[HID];
__device__ float2 g_ab[NSEG * HID];         // per (outer seg, j): (alpha, beta)
__device__ float  g_kinks[NSEG * HID];      // per outer seg: sorted inner kinks
__device__ int    g_m[NSEG];                // # inner kinks per outer seg
__device__ int    g_K;                      // final segment count
__device__ float  g_flatT[KMAX];            // sorted global breakpoints
__device__ float2 g_flatAB[KMAX];           // (A, B+b3) per final segment
__device__ unsigned short g_lut[LUTE];      // ordered-bin -> segment lower bound

// ordered-float transform: monotone uint key (non-NaN floats)
__device__ __forceinline__ unsigned okey(float f) {
    unsigned u = __float_as_uint(f);
    return (u & 0x80000000u) ? ~u : (u | 0x80000000u);
}

// ============================================================================
// Setup 1: 129 blocks x 512 threads. thread = (j, q); q splits the i-loop 4x.
// ============================================================================
__global__ void setup_seg(const float* __restrict__ w1,
                          const float* __restrict__ b1,
                          const float* __restrict__ w2,
                          const float* __restrict__ b2) {
    __shared__ float sw1[HID], sb1[HID], ssort[HID], su[HID];
    __shared__ float spa[4][HID], spb[4][HID];
    __shared__ int   sval[HID];
    int t = threadIdx.x;
    int j = t & (HID - 1);
    int q = t >> 7;
    int s = blockIdx.x;

    if (q == 0) {
        float w = w1[j], b = b1[j];
        sw1[j] = w; sb1[j] = b;
        su[j] = -b / w;                       // kink t_j (temp in su)
    }
    __syncthreads();
    if (q == 0) {
        float tj = su[j];
        int rank = 0;
        #pragma unroll 8
        for (int k = 0; k < HID; k++) {
            float tk = su[k];
            rank += (tk < tj) || (tk == tj && k < j);
        }
        ssort[rank] = tj;
    }
    __syncthreads();
    if (s == 0 && t < HID) g_sorted_t[t] = ssort[t];

    float lo = (s == 0)   ? -FLT_MAX : ssort[s - 1];
    float hi = (s == HID) ?  FLT_MAX : ssort[s];
    float Fm = (s == 0)   ? ssort[0] - 1.0f
             : (s == HID) ? ssort[HID - 1] + 1.0f
                          : 0.5f * (lo + hi);

    float pa = 0.0f, pb = 0.0f;
    #pragma unroll
    for (int ii = 0; ii < 32; ii++) {
        int i = q * 32 + ii;
        float wi = sw1[i], bi = sb1[i];
        bool act = fmaf(wi, Fm, bi) > 0.0f;
        float w2ij = __ldg(&w2[i * HID + j]);
        pa = fmaf(act ? wi : 0.0f, w2ij, pa);
        pb = fmaf(act ? bi : 0.0f, w2ij, pb);
    }
    spa[q][j] = pa; spb[q][j] = pb;
    __syncthreads();

    if (q == 0) {
        float alpha = (spa[0][j] + spa[1][j]) + (spa[2][j] + spa[3][j]);
        float beta  = (spb[0][j] + spb[1][j]) + (spb[2][j] + spb[3][j]) + b2[j];
        g_ab[s * HID + j] = make_float2(alpha, beta);
        float u = -beta / alpha;
        bool valid = (alpha != 0.0f) && (u > lo) && (u < hi);   // NaN -> false
        su[j]   = valid ? u : FLT_MAX;
        sval[j] = valid ? 1 : 0;
    }
    __syncthreads();
    if (q == 0) {
        int m = 0, r = 0;
        float uj = su[j];
        #pragma unroll 8
        for (int k = 0; k < HID; k++) {
            m += sval[k];
            float uk = su[k];
            r += (uk < uj) || (uk == uj && k < j);
        }
        if (sval[j]) g_kinks[s * HID + r] = su[j];
        if (j == 0) g_m[s] = m;
    }
}

// ============================================================================
// Setup 2: flat table build; offsets via replicated in-block scan of g_m.
// ============================================================================
__global__ void setup_final(const float* __restrict__ w3,
                            const float* __restrict__ b3) {
    int s = blockIdx.x;
    int t = threadIdx.x;
    __shared__ int sm_scan[NSEG];
    if (t < NSEG) sm_scan[t] = g_m[t];
    __syncthreads();
    #pragma unroll
    for (int d = 1; d < 256; d <<= 1) {
        int v = (t >= d && t < NSEG) ? sm_scan[t - d] : 0;
        __syncthreads();
        if (t < NSEG) sm_scan[t] += v;
        __syncthreads();
    }
    if (s == 0 && t == 0) g_K = NSEG + sm_scan[NSEG - 1];

    int off  = s + (s ? sm_scan[s - 1] : 0);
    int nsub = g_m[s] + 1;
    float segLo = (s == 0)   ? -FLT_MAX : g_sorted_t[s - 1];
    float segHi = (s == HID) ?  FLT_MAX : g_sorted_t[s];
    float b3v = b3[0];
    int wid = t >> 5, lane = t & 31;

    for (int r = wid; r < nsub; r += 8) {
        float lo_r = (r == 0)        ? segLo : g_kinks[s * HID + r - 1];
        float hi_r = (r == nsub - 1) ? segHi : g_kinks[s * HID + r];
        float Fm;
        if (lo_r == -FLT_MAX)      Fm = hi_r - 1.0f;
        else if (hi_r == FLT_MAX)  Fm = lo_r + 1.0f;
        else                       Fm = 0.5f * (lo_r + hi_r);

        float A = 0.0f, B = 0.0f;
        #pragma unroll
        for (int q = lane; q < HID; q += 32) {
            float2 ab = g_ab[s * HID + q];
            if (fmaf(ab.x, Fm, ab.y) > 0.0f) {
                float w3q = __ldg(&w3[q]);
                A = fmaf(w3q, ab.x, A);
                B = fmaf(w3q, ab.y, B);
            }
        }
        #pragma unroll
        for (int d = 16; d; d >>= 1) {
            A += __shfl_xor_sync(0xffffffffu, A, d);
            B += __shfl_xor_sync(0xffffffffu, B, d);
        }
        if (lane == 0) {
            g_flatT[off + r]  = lo_r;
            g_flatAB[off + r] = make_float2(A, B + b3v);
        }
    }
}

// ============================================================================
// Setup 3: lut[b] = largest s with flatT[s] <= edgeFloat(b<<19), edges taken
// over the ordered-float space (data-independent, monotone, outlier-proof).
// ============================================================================
__global__ void setup_lut() {
    int b = blockIdx.x * blockDim.x + threadIdx.x;
    if (b >= LUTE) return;
    int K = g_K;
    int res;
    if (b == LUTN) {
        res = K - 1;
    } else {
        unsigned k = (unsigned)b << (32 - LUTBITS);
        unsigned u = (k & 0x80000000u) ? (k & 0x7FFFFFFFu) : ~k;
        float edge = __uint_as_float(u);
        if (isnan(edge)) {
            res = (k & 0x80000000u) ? K - 1 : 0;
        } else {
            int a = 0, c = K - 1;
            while (a < c) {
                int mid = (a + c + 1) >> 1;
                if (g_flatT[mid] <= edge) a = mid; else c = mid - 1;
            }
            res = a;
        }
    }
    g_lut[b] = (unsigned short)res;
}

// ============================================================================
// Main kernel
// ============================================================================
__device__ __forceinline__ float interp_fast(const float* __restrict__ pl,
                                             int i1, float h, int i2, float v) {
    const float* p0 = pl + i1 * RES + i2;
    float bl = __ldg(p0);
    float tl = __ldg(p0 + 1);
    float br = __ldg(p0 + RES);
    float tr = __ldg(p0 + RES + 1);
    float bottom = fmaf(br - bl, h, bl);
    float top    = fmaf(tr - tl, h, tl);
    return fmaf(top - bottom, v, bottom);
}

__device__ __forceinline__ float eval_point(
    float px, float py, float pz,
    const float* __restrict__ xy, const float* __restrict__ yz,
    const float* __restrict__ xz,
    const float* sT, const unsigned short* sLut) {

    float cx = fmaf(px, 255.5f, 255.5f);   // (p+1)*0.5*511 in [0,511)
    float cy = fmaf(py, 255.5f, 255.5f);
    float cz = fmaf(pz, 255.5f, 255.5f);
    int ix = min((int)cx, RES - 2);
    int iy = min((int)cy, RES - 2);
    int iz = min((int)cz, RES - 2);
    float hx = cx - (float)ix;
    float hy = cy - (float)iy;
    float hz = cz - (float)iz;

    float F = interp_fast(xy, ix, hx, iy, hy)
            + interp_fast(xz, ix, hx, iz, hz)
            + interp_fast(yz, iy, hy, iz, hz);

    int b = (int)(okey(F) >> (32 - LUTBITS));
    int lo = (int)sLut[b];
    int hi = (int)sLut[b + 1];
    while (lo < hi) {
        int mid = (lo + hi + 1) >> 1;
        bool le = sT[mid] <= F;
        lo = le ? mid : lo;
        hi = le ? hi  : mid - 1;
    }
    float2 ab = __ldg(&g_flatAB[lo]);
    float r;
    asm("tanh.approx.f32 %0, %1;" : "=f"(r) : "f"(fmaf(ab.x, F, ab.y)));
    return r;
}

__global__ __launch_bounds__(1024, 1)
void neusdf_main(const float* __restrict__ points,
                 const float* __restrict__ xy,
                 const float* __restrict__ yz,
                 const float* __restrict__ xz,
                 float* __restrict__ out, int N) {
    extern __shared__ float sm[];
    float*          sT   = sm;                              // [K] breakpoints
    unsigned short* sLut = (unsigned short*)(sm + KPAD);    // [LUTE]
    __shared__ int sK;
    if (threadIdx.x == 0) sK = g_K;
    __syncthreads();
    int K = sK;
    for (int i = threadIdx.x; i < K; i += 1024) sT[i] = g_flatT[i];
    for (int i = threadIdx.x; i < LUTE; i += 1024) sLut[i] = g_lut[i];
    __syncthreads();

    const float2* pp = (const float2*)points;
    float2*       op = (float2*)out;
    int G = N >> 1;
    int gstride = gridDim.x * blockDim.x;

    for (int g = blockIdx.x * blockDim.x + threadIdx.x; g < G; g += gstride) {
        float2 u = pp[3 * g + 0];
        float2 v = pp[3 * g + 1];
        float2 w = pp[3 * g + 2];
        float o0 = eval_point(u.x, u.y, v.x, xy, yz, xz, sT, sLut);
        float o1 = eval_point(v.y, w.x, w.y, xy, yz, xz, sT, sLut);
        op[g] = make_float2(o0, o1);
    }
    if ((N & 1) && blockIdx.x == 0 && threadIdx.x == 0) {
        int i = N - 1;
        out[i] = eval_point(points[3*i], points[3*i+1], points[3*i+2],
                            xy, yz, xz, sT, sLut);
    }
}

// ============================================================================
extern "C" void kernel_launch(void* const* d_in, const int* in_sizes, int n_in,
                              void* d_out, int out_size) {
    const float* points = (const float*)d_in[0];
    const float* xy     = (const float*)d_in[1];
    const float* yz     = (const float*)d_in[2];
    const float* xz     = (const float*)d_in[3];
    const float* w1     = (const float*)d_in[4];
    const float* b1     = (const float*)d_in[5];
    const float* w2     = (const float*)d_in[6];
    const float* b2     = (const float*)d_in[7];
    const float* w3     = (const float*)d_in[8];
    const float* b3     = (const float*)d_in[9];
    int N = in_sizes[0] / 3;

    setup_seg  <<<NSEG, 512>>>(w1, b1, w2, b2);
    setup_final<<<NSEG, 256>>>(w3, b3);
    setup_lut  <<<(LUTE + 511) / 512, 512>>>();

    size_t smem = sizeof(float) * KPAD + sizeof(unsigned short) * (LUTE + 1);
    cudaFuncSetAttribute(neusdf_main,
                         cudaFuncAttributeMaxDynamicSharedMemorySize,
                         (int)smem);

    int nsm = 148;
    cudaDeviceGetAttribute(&nsm, cudaDevAttrMultiProcessorCount, 0);

    neusdf_main<<<nsm, 1024, smem>>>(points, xy, yz, xz, (float*)d_out, N);
}

// round 5
// speedup vs baseline: 3.0715x; 1.6141x over previous
#include <cuda_runtime.h>
#include <math.h>
#include <float.h>

#define RES   512
#define HID   128
#define NSEG  (HID + 1)            // 129 outer segments
#define KMAX  (NSEG + HID * NSEG)  // 16641 worst-case final segments
#define KPAD  16642
#define LUTBITS 13
#define LUTN  (1 << LUTBITS)       // 8192 bins over ordered-float space
#define LUTE  (LUTN + 1)           // 8193 boundary entries

// ---------------- persistent device tables (rebuilt every launch) ----------
__device__ float  g_sorted_t[HID];
__device__ float2 g_ab[NSEG * HID];         // per (outer seg, j): (alpha, beta)
__device__ float  g_kinks[NSEG * HID];      // per outer seg: sorted inner kinks
__device__ int    g_m[NSEG];                // # inner kinks per outer seg
__device__ int    g_K;                      // final segment count
__device__ float  g_flatT[KMAX];            // sorted global breakpoints
__device__ float2 g_flatAB[KMAX];           // (A, B+b3) per final segment
__device__ unsigned short g_lut[LUTE];      // ordered-bin -> segment lower bound
__device__ float4 g_quad[3 * 512 * 512];    // 2x2 corner quads per plane (12MB)

// ordered-float transform: monotone uint key (non-NaN floats)
__device__ __forceinline__ unsigned okey(float f) {
    unsigned u = __float_as_uint(f);
    return (u & 0x80000000u) ? ~u : (u | 0x80000000u);
}

// ============================================================================
// Quad builder: g_quad[p][i][j] = {pl[i][j], pl[i][j+1], pl[i+1][j], pl[i+1][j+1]}
// ============================================================================
__global__ void build_quads(const float* __restrict__ xy,
                            const float* __restrict__ yz,
                            const float* __restrict__ xz) {
    int p = blockIdx.y;
    int i = blockIdx.x;                       // 0..510
    int j = threadIdx.x;                      // 0..511
    if (j >= RES - 1) return;
    const float* pl = (p == 0) ? xy : (p == 1) ? yz : xz;
    const float* r0 = pl + i * RES;
    float4 q = make_float4(r0[j], r0[j + 1], r0[j + RES], r0[j + RES + 1]);
    g_quad[(p << 18) + (i << 9) + j] = q;
}

// ============================================================================
// Setup 1: 129 blocks x 512 threads. thread = (j, q); q splits the i-loop 4x.
// ============================================================================
__global__ void setup_seg(const float* __restrict__ w1,
                          const float* __restrict__ b1,
                          const float* __restrict__ w2,
                          const float* __restrict__ b2) {
    __shared__ float sw1[HID], sb1[HID], ssort[HID], su[HID];
    __shared__ float spa[4][HID], spb[4][HID];
    __shared__ int   sval[HID];
    int t = threadIdx.x;
    int j = t & (HID - 1);
    int q = t >> 7;
    int s = blockIdx.x;

    if (q == 0) {
        float w = w1[j], b = b1[j];
        sw1[j] = w; sb1[j] = b;
        su[j] = -b / w;
    }
    __syncthreads();
    if (q == 0) {
        float tj = su[j];
        int rank = 0;
        #pragma unroll 8
        for (int k = 0; k < HID; k++) {
            float tk = su[k];
            rank += (tk < tj) || (tk == tj && k < j);
        }
        ssort[rank] = tj;
    }
    __syncthreads();
    if (s == 0 && t < HID) g_sorted_t[t] = ssort[t];

    float lo = (s == 0)   ? -FLT_MAX : ssort[s - 1];
    float hi = (s == HID) ?  FLT_MAX : ssort[s];
    float Fm = (s == 0)   ? ssort[0] - 1.0f
             : (s == HID) ? ssort[HID - 1] + 1.0f
                          : 0.5f * (lo + hi);

    float pa = 0.0f, pb = 0.0f;
    #pragma unroll
    for (int ii = 0; ii < 32; ii++) {
        int i = q * 32 + ii;
        float wi = sw1[i], bi = sb1[i];
        bool act = fmaf(wi, Fm, bi) > 0.0f;
        float w2ij = __ldg(&w2[i * HID + j]);
        pa = fmaf(act ? wi : 0.0f, w2ij, pa);
        pb = fmaf(act ? bi : 0.0f, w2ij, pb);
    }
    spa[q][j] = pa; spb[q][j] = pb;
    __syncthreads();

    if (q == 0) {
        float alpha = (spa[0][j] + spa[1][j]) + (spa[2][j] + spa[3][j]);
        float beta  = (spb[0][j] + spb[1][j]) + (spb[2][j] + spb[3][j]) + b2[j];
        g_ab[s * HID + j] = make_float2(alpha, beta);
        float u = -beta / alpha;
        bool valid = (alpha != 0.0f) && (u > lo) && (u < hi);   // NaN -> false
        su[j]   = valid ? u : FLT_MAX;
        sval[j] = valid ? 1 : 0;
    }
    __syncthreads();
    if (q == 0) {
        int m = 0, r = 0;
        float uj = su[j];
        #pragma unroll 8
        for (int k = 0; k < HID; k++) {
            m += sval[k];
            float uk = su[k];
            r += (uk < uj) || (uk == uj && k < j);
        }
        if (sval[j]) g_kinks[s * HID + r] = su[j];
        if (j == 0) g_m[s] = m;
    }
}

// ============================================================================
// Setup 2: flat table build; offsets via replicated in-block scan of g_m.
// ============================================================================
__global__ void setup_final(const float* __restrict__ w3,
                            const float* __restrict__ b3) {
    int s = blockIdx.x;
    int t = threadIdx.x;
    __shared__ int sm_scan[NSEG];
    if (t < NSEG) sm_scan[t] = g_m[t];
    __syncthreads();
    #pragma unroll
    for (int d = 1; d < 256; d <<= 1) {
        int v = (t >= d && t < NSEG) ? sm_scan[t - d] : 0;
        __syncthreads();
        if (t < NSEG) sm_scan[t] += v;
        __syncthreads();
    }
    if (s == 0 && t == 0) g_K = NSEG + sm_scan[NSEG - 1];

    int off  = s + (s ? sm_scan[s - 1] : 0);
    int nsub = g_m[s] + 1;
    float segLo = (s == 0)   ? -FLT_MAX : g_sorted_t[s - 1];
    float segHi = (s == HID) ?  FLT_MAX : g_sorted_t[s];
    float b3v = b3[0];
    int wid = t >> 5, lane = t & 31;

    for (int r = wid; r < nsub; r += 8) {
        float lo_r = (r == 0)        ? segLo : g_kinks[s * HID + r - 1];
        float hi_r = (r == nsub - 1) ? segHi : g_kinks[s * HID + r];
        float Fm;
        if (lo_r == -FLT_MAX)      Fm = hi_r - 1.0f;
        else if (hi_r == FLT_MAX)  Fm = lo_r + 1.0f;
        else                       Fm = 0.5f * (lo_r + hi_r);

        float A = 0.0f, B = 0.0f;
        #pragma unroll
        for (int q = lane; q < HID; q += 32) {
            float2 ab = g_ab[s * HID + q];
            if (fmaf(ab.x, Fm, ab.y) > 0.0f) {
                float w3q = __ldg(&w3[q]);
                A = fmaf(w3q, ab.x, A);
                B = fmaf(w3q, ab.y, B);
            }
        }
        #pragma unroll
        for (int d = 16; d; d >>= 1) {
            A += __shfl_xor_sync(0xffffffffu, A, d);
            B += __shfl_xor_sync(0xffffffffu, B, d);
        }
        if (lane == 0) {
            g_flatT[off + r]  = lo_r;
            g_flatAB[off + r] = make_float2(A, B + b3v);
        }
    }
}

// ============================================================================
// Setup 3: lut[b] = largest s with flatT[s] <= edge(b) over ordered-float space
// ============================================================================
__global__ void setup_lut() {
    int b = blockIdx.x * blockDim.x + threadIdx.x;
    if (b >= LUTE) return;
    int K = g_K;
    int res;
    if (b == LUTN) {
        res = K - 1;
    } else {
        unsigned k = (unsigned)b << (32 - LUTBITS);
        unsigned u = (k & 0x80000000u) ? (k & 0x7FFFFFFFu) : ~k;
        float edge = __uint_as_float(u);
        if (isnan(edge)) {
            res = (k & 0x80000000u) ? K - 1 : 0;
        } else {
            int a = 0, c = K - 1;
            while (a < c) {
                int mid = (a + c + 1) >> 1;
                if (g_flatT[mid] <= edge) a = mid; else c = mid - 1;
            }
            res = a;
        }
    }
    g_lut[b] = (unsigned short)res;
}

// ============================================================================
// Main kernel
// ============================================================================
__device__ __forceinline__ float quad_lerp(float4 q, float h, float v) {
    // q = {bl, tl, br, tr} at (i,j),(i,j+1),(i+1,j),(i+1,j+1); h along i, v along j
    float bottom = fmaf(q.z - q.x, h, q.x);
    float top    = fmaf(q.w - q.y, h, q.y);
    return fmaf(top - bottom, v, bottom);
}

__device__ __forceinline__ float eval_point(
    float px, float py, float pz,
    const float* sT, const unsigned short* sLut) {

    float cx = fmaf(px, 255.5f, 255.5f);   // (p+1)*0.5*511 in [0,511)
    float cy = fmaf(py, 255.5f, 255.5f);
    float cz = fmaf(pz, 255.5f, 255.5f);
    int ix = min((int)cx, RES - 2);
    int iy = min((int)cy, RES - 2);
    int iz = min((int)cz, RES - 2);
    float hx = cx - (float)ix;
    float hy = cy - (float)iy;
    float hz = cz - (float)iz;

    // one aligned float4 gather per plane (all three independent -> MLP=3)
    float4 qxy = __ldg(&g_quad[           (ix << 9) + iy]);
    float4 qyz = __ldg(&g_quad[(1 << 18) + (iy << 9) + iz]);
    float4 qxz = __ldg(&g_quad[(2 << 18) + (ix << 9) + iz]);

    float F = quad_lerp(qxy, hx, hy)
            + quad_lerp(qxz, hx, hz)
            + quad_lerp(qyz, hy, hz);

    int b = (int)(okey(F) >> (32 - LUTBITS));
    int lo = (int)sLut[b];
    int hi = (int)sLut[b + 1];
    while (lo < hi) {
        int mid = (lo + hi + 1) >> 1;
        bool le = sT[mid] <= F;
        lo = le ? mid : lo;
        hi = le ? hi  : mid - 1;
    }
    float2 ab = __ldg(&g_flatAB[lo]);
    float r;
    asm("tanh.approx.f32 %0, %1;" : "=f"(r) : "f"(fmaf(ab.x, F, ab.y)));
    return r;
}

__global__ __launch_bounds__(1024, 1)
void neusdf_main(const float* __restrict__ points,
                 float* __restrict__ out, int N) {
    extern __shared__ float sm[];
    float*          sT   = sm;                              // [K] breakpoints
    unsigned short* sLut = (unsigned short*)(sm + KPAD);    // [LUTE]
    __shared__ int sK;
    if (threadIdx.x == 0) sK = g_K;
    __syncthreads();
    int K = sK;
    for (int i = threadIdx.x; i < K; i += 1024) sT[i] = g_flatT[i];
    for (int i = threadIdx.x; i < LUTE; i += 1024) sLut[i] = g_lut[i];
    __syncthreads();

    const float2* pp = (const float2*)points;
    float2*       op = (float2*)out;
    int G = N >> 1;
    int gstride = gridDim.x * blockDim.x;

    for (int g = blockIdx.x * blockDim.x + threadIdx.x; g < G; g += gstride) {
        float2 u = pp[3 * g + 0];
        float2 v = pp[3 * g + 1];
        float2 w = pp[3 * g + 2];
        float o0 = eval_point(u.x, u.y, v.x, sT, sLut);
        float o1 = eval_point(v.y, w.x, w.y, sT, sLut);
        op[g] = make_float2(o0, o1);
    }
    if ((N & 1) && blockIdx.x == 0 && threadIdx.x == 0) {
        int i = N - 1;
        out[i] = eval_point(points[3*i], points[3*i+1], points[3*i+2], sT, sLut);
    }
}

// ============================================================================
extern "C" void kernel_launch(void* const* d_in, const int* in_sizes, int n_in,
                              void* d_out, int out_size) {
    const float* points = (const float*)d_in[0];
    const float* xy     = (const float*)d_in[1];
    const float* yz     = (const float*)d_in[2];
    const float* xz     = (const float*)d_in[3];
    const float* w1     = (const float*)d_in[4];
    const float* b1     = (const float*)d_in[5];
    const float* w2     = (const float*)d_in[6];
    const float* b2     = (const float*)d_in[7];
    const float* w3     = (const float*)d_in[8];
    const float* b3     = (const float*)d_in[9];
    int N = in_sizes[0] / 3;

    dim3 qgrid(RES - 1, 3);
    build_quads<<<qgrid, RES>>>(xy, yz, xz);
    setup_seg  <<<NSEG, 512>>>(w1, b1, w2, b2);
    setup_final<<<NSEG, 256>>>(w3, b3);
    setup_lut  <<<(LUTE + 511) / 512, 512>>>();

    size_t smem = sizeof(float) * KPAD + sizeof(unsigned short) * (LUTE + 1);
    cudaFuncSetAttribute(neusdf_main,
                         cudaFuncAttributeMaxDynamicSharedMemorySize,
                         (int)smem);

    int nsm = 148;
    cudaDeviceGetAttribute(&nsm, cudaDevAttrMultiProcessorCount, 0);

    neusdf_main<<<nsm, 1024, smem>>>(points, (float*)d_out, N);
}